// round 8
// baseline (speedup 1.0000x reference)
#include <cuda_runtime.h>
#include <cuda_fp16.h>
#include <cstdint>
#include <math_constants.h>

// ---------------------------------------------------------------------------
// spk_vq_vae_resnet — f16-accumulator HMMA round.
// argmin: fp16 mma.sync with f16 accum (2x rate hypothesis), 128-code tiles,
// occ 2, top-3 band (4e-3) + 2-tier exact rescue. CSR deterministic EMA sums.
// Outputs (concat f32): st_out [N*D], commit_loss [1], w_new [K*D], c_new [K]
// ---------------------------------------------------------------------------

#define VQ_ALPHA 0.99f
#define VQ_OMA   0.01f

constexpr int D    = 128;
constexpr int NMAX = 65536;
constexpr int KMAX = 2048;
constexpr int NTILE = 16;          // code tiles of 128
constexpr float BAND = 4e-3f;      // widened for f16 accumulation error

// ---- device scratch -------------------------------------------------------
__device__ __align__(16) __half g_Zh[NMAX * D];
__device__ __align__(16) __half g_Wh[KMAX * D];
__device__ float  g_w2[KMAX];
__device__ int    g_idx[NMAX];
__device__ int    g_f1row[NMAX], g_f1a[NMAX], g_f1b[NMAX];
__device__ int    g_f2row[NMAX];
__device__ int    g_n1, g_n2;
__device__ int    g_counts[KMAX];
__device__ int    g_off[KMAX];
__device__ int    g_cursor[KMAX];
__device__ int    g_bucket[NMAX];
__device__ double g_loss;

// ---- helpers --------------------------------------------------------------
__device__ __forceinline__ uint32_t smem_u32(const void* p) {
    uint32_t a;
    asm("{ .reg .u64 t; cvta.to.shared.u64 t, %1; cvt.u32.u64 %0, t; }"
        : "=r"(a) : "l"(p));
    return a;
}
__device__ __forceinline__ void cp_async16(uint32_t smem_dst, const void* gsrc) {
    asm volatile("cp.async.cg.shared.global [%0], [%1], 16;" :: "r"(smem_dst), "l"(gsrc));
}
__device__ __forceinline__ void cp_commit() { asm volatile("cp.async.commit_group;"); }
template <int NN>
__device__ __forceinline__ void cp_wait() { asm volatile("cp.async.wait_group %0;" :: "n"(NN)); }

__device__ __forceinline__ void ldsm4(uint32_t& r0, uint32_t& r1, uint32_t& r2,
                                      uint32_t& r3, uint32_t addr) {
    asm volatile("ldmatrix.sync.aligned.m8n8.x4.shared.b16 {%0,%1,%2,%3}, [%4];"
                 : "=r"(r0), "=r"(r1), "=r"(r2), "=r"(r3) : "r"(addr));
}
// f16-accumulator mma: C/D are 2 regs (each = __half2)
__device__ __forceinline__ void mma16816_f16(uint32_t* c, uint32_t a0, uint32_t a1,
                                             uint32_t a2, uint32_t a3,
                                             uint32_t b0, uint32_t b1) {
    asm volatile(
        "mma.sync.aligned.m16n8k16.row.col.f16.f16.f16.f16 "
        "{%0,%1}, {%2,%3,%4,%5}, {%6,%7}, {%0,%1};"
        : "+r"(c[0]), "+r"(c[1])
        : "r"(a0), "r"(a1), "r"(a2), "r"(a3), "r"(b0), "r"(b1));
}

// top-3 insert with lowest-index tie preference
__device__ __forceinline__ void ins3(float s, int c,
                                     float& b1, int& i1, float& b2, int& i2,
                                     float& b3, int& i3) {
    if (s < b1 || (s == b1 && c < i1)) {
        b3 = b2; i3 = i2; b2 = b1; i2 = i1; b1 = s; i1 = c;
    } else if (s < b2 || (s == b2 && c < i2)) {
        b3 = b2; i3 = i2; b2 = s; i2 = c;
    } else if (s < b3 || (s == b3 && c < i3)) {
        b3 = s; i3 = c;
    }
}

// ---------------------------------------------------------------------------

__global__ void zero_kernel(int K) {
    int i = blockIdx.x * blockDim.x + threadIdx.x;
    int stride = gridDim.x * blockDim.x;
    for (int j = i; j < K; j += stride) { g_counts[j] = 0; g_cursor[j] = 0; }
    if (i == 0) { g_loss = 0.0; g_n1 = 0; g_n2 = 0; }
}

// fp32 -> fp16 conversion for Z and W; w2 for W rows.
__global__ void prep_kernel(const float* __restrict__ Z,
                            const float* __restrict__ W, int N, int K) {
    int g    = (blockIdx.x * blockDim.x + threadIdx.x) >> 5;
    int lane = threadIdx.x & 31;
    if (g >= N + K) return;
    const float* src;
    __half* dst;
    bool isW = (g >= N);
    if (!isW) { src = Z + (size_t)g * D;        dst = g_Zh + (size_t)g * D; }
    else      { src = W + (size_t)(g - N) * D;  dst = g_Wh + (size_t)(g - N) * D; }
    float4 v = ((const float4*)src)[lane];
    __half2 h01 = __floats2half2_rn(v.x, v.y);
    __half2 h23 = __floats2half2_rn(v.z, v.w);
    uint2 u = { *(uint32_t*)&h01, *(uint32_t*)&h23 };
    *(uint2*)(dst + lane * 4) = u;
    if (isW) {
        float s = 0.f;
        s = fmaf(v.x, v.x, s); s = fmaf(v.y, v.y, s);
        s = fmaf(v.z, v.z, s); s = fmaf(v.w, v.w, s);
        #pragma unroll
        for (int off = 16; off; off >>= 1) s += __shfl_xor_sync(0xffffffffu, s, off);
        if (lane == 0) g_w2[g - N] = s;
    }
}

// ---- fp16 HMMA argmin, f16 accum, 128-code tiles, 2 CTAs/SM ---------------
// smem: Zs 32KB | Bs 2x32KB | w2s 8KB = 106496 B
constexpr int SM_Z  = 0;
constexpr int SM_B0 = 32768;
constexpr int SM_W2 = 98304;
constexpr int SMEM_ARG = SM_W2 + KMAX * 4;   // 106496 bytes

// swizzled chunk store address: row-major rows of 16 chunks (16B each)
__device__ __forceinline__ uint32_t sw_addr(uint32_t base, int r, int c) {
    return base + r * 256 + ((c ^ (r & 7)) << 4);
}

__global__ __launch_bounds__(256, 2)
void argmin_hmma_kernel() {
    extern __shared__ char sm[];
    const uint32_t sb = smem_u32(sm);
    float* w2s = (float*)(sm + SM_W2);
    const int tid  = threadIdx.x;
    const int lane = tid & 31;
    const int wid  = tid >> 5;
    const int warpRow = wid * 16;
    const int row0 = blockIdx.x * 128;

    for (int i = tid; i < KMAX; i += 256) w2s[i] = g_w2[i];

    // group 0: Z tile + B tile 0
    for (int i = tid; i < 2048; i += 256) {
        int r = i >> 4, c = i & 15;
        cp_async16(sw_addr(sb + SM_Z, r, c), g_Zh + (size_t)(row0 + r) * D + c * 8);
    }
    for (int i = tid; i < 2048; i += 256) {
        int r = i >> 4, c = i & 15;
        cp_async16(sw_addr(sb + SM_B0, r, c), g_Wh + (size_t)r * D + c * 8);
    }
    cp_commit();
    // group 1: B tile 1
    for (int i = tid; i < 2048; i += 256) {
        int r = i >> 4, c = i & 15;
        cp_async16(sw_addr(sb + SM_B0 + 32768, r, c),
                   g_Wh + (size_t)(128 + r) * D + c * 8);
    }
    cp_commit();

    float B1[2] = {CUDART_INF_F, CUDART_INF_F};
    float B2[2] = {CUDART_INF_F, CUDART_INF_F};
    float B3[2] = {CUDART_INF_F, CUDART_INF_F};
    int   I1[2] = {0x7fffffff, 0x7fffffff};
    int   I2[2] = {0x7fffffff, 0x7fffffff};
    int   I3[2] = {0x7fffffff, 0x7fffffff};

    const int m  = lane >> 3;
    const int r8 = lane & 7;

    for (int t = 0; t < NTILE; t++) {
        if (t < NTILE - 1) cp_wait<1>(); else cp_wait<0>();
        __syncthreads();                       // B[t] visible to all warps
        const uint32_t bbase = sb + SM_B0 + (t & 1) * 32768;

        uint32_t acc[16][2];
        #pragma unroll
        for (int f = 0; f < 16; f++) { acc[f][0] = 0u; acc[f][1] = 0u; }

        #pragma unroll
        for (int ks = 0; ks < 8; ks++) {
            uint32_t a0, a1, a2, a3;
            {
                int row = warpRow + ((m & 1) << 3) + r8;
                int ch  = 2 * ks + (m >> 1);
                ldsm4(a0, a1, a2, a3, sw_addr(sb + SM_Z, row, ch));
            }
            #pragma unroll
            for (int nf = 0; nf < 16; nf += 2) {
                uint32_t c0, c1, c2, c3;
                {
                    int code = nf * 8 + ((m >> 1) << 3) + r8;
                    int ch   = 2 * ks + (m & 1);
                    ldsm4(c0, c1, c2, c3, sw_addr(bbase, code, ch));
                }
                mma16816_f16(acc[nf],     a0, a1, a2, a3, c0, c1);
                mma16816_f16(acc[nf + 1], a0, a1, a2, a3, c2, c3);
            }
        }

        __syncthreads();                       // all warps done reading B[t]

        // prefetch tile t+2 into this buffer; overlap with epilogue
        if (t < NTILE - 2) {
            const __half* src = g_Wh + (size_t)(t + 2) * 128 * D;
            uint32_t dstb = sb + SM_B0 + (t & 1) * 32768;
            for (int i = tid; i < 2048; i += 256) {
                int r = i >> 4, c = i & 15;
                cp_async16(sw_addr(dstb, r, c), src + (size_t)r * D + c * 8);
            }
            cp_commit();
        }

        // epilogue: s = w2 - 2*zw ; acc[f][0] = row r0 cols (cb0,cb0+1),
        // acc[f][1] = row r1 (= r0+8) same cols, packed as __half2.
        #pragma unroll
        for (int f = 0; f < 16; f++) {
            int cb0 = t * 128 + f * 8 + 2 * (lane & 3);
            float w2a = w2s[cb0], w2b = w2s[cb0 + 1];
            float2 p0 = __half22float2(*(__half2*)&acc[f][0]);
            float2 p1 = __half22float2(*(__half2*)&acc[f][1]);
            float s;
            s = fmaf(-2.f, p0.x, w2a);
            ins3(s, cb0,     B1[0], I1[0], B2[0], I2[0], B3[0], I3[0]);
            s = fmaf(-2.f, p0.y, w2b);
            ins3(s, cb0 + 1, B1[0], I1[0], B2[0], I2[0], B3[0], I3[0]);
            s = fmaf(-2.f, p1.x, w2a);
            ins3(s, cb0,     B1[1], I1[1], B2[1], I2[1], B3[1], I3[1]);
            s = fmaf(-2.f, p1.y, w2b);
            ins3(s, cb0 + 1, B1[1], I1[1], B2[1], I2[1], B3[1], I3[1]);
        }
    }

    // merge across the 4 lanes of each quad (same rows)
    #pragma unroll
    for (int off = 1; off <= 2; off <<= 1) {
        #pragma unroll
        for (int r = 0; r < 2; r++) {
            float v1 = __shfl_xor_sync(0xffffffffu, B1[r], off);
            int   j1 = __shfl_xor_sync(0xffffffffu, I1[r], off);
            float v2 = __shfl_xor_sync(0xffffffffu, B2[r], off);
            int   j2 = __shfl_xor_sync(0xffffffffu, I2[r], off);
            float v3 = __shfl_xor_sync(0xffffffffu, B3[r], off);
            int   j3 = __shfl_xor_sync(0xffffffffu, I3[r], off);
            ins3(v1, j1, B1[r], I1[r], B2[r], I2[r], B3[r], I3[r]);
            ins3(v2, j2, B1[r], I1[r], B2[r], I2[r], B3[r], I3[r]);
            ins3(v3, j3, B1[r], I1[r], B2[r], I2[r], B3[r], I3[r]);
        }
    }

    if ((lane & 3) == 0) {
        #pragma unroll
        for (int r = 0; r < 2; r++) {
            int row = row0 + warpRow + (lane >> 2) + r * 8;
            g_idx[row] = I1[r];
            if (__fsub_rn(B3[r], B1[r]) < BAND) {
                int p = atomicAdd(&g_n2, 1);
                g_f2row[p] = row;
            } else if (__fsub_rn(B2[r], B1[r]) < BAND) {
                int p = atomicAdd(&g_n1, 1);
                g_f1row[p] = row; g_f1a[p] = I1[r]; g_f1b[p] = I2[r];
            }
        }
    }
}

// ---- tier 1: exact fp32 compare of the two candidates ----------------------
__global__ void tier1_kernel(const float* __restrict__ Z,
                             const float* __restrict__ W) {
    int n1 = g_n1;
    int wg = (blockIdx.x * blockDim.x + threadIdx.x) >> 5;
    int lane = threadIdx.x & 31;
    int nwarps = (gridDim.x * blockDim.x) >> 5;
    for (int e = wg; e < n1; e += nwarps) {
        int row = g_f1row[e], ca = g_f1a[e], cb = g_f1b[e];
        float4 zv = ((const float4*)(Z + (size_t)row * D))[lane];
        float4 av = ((const float4*)(W + (size_t)ca * D))[lane];
        float4 bv = ((const float4*)(W + (size_t)cb * D))[lane];
        float z2 = 0.f, da = 0.f, db = 0.f;
        z2 = fmaf(zv.x, zv.x, z2); z2 = fmaf(zv.y, zv.y, z2);
        z2 = fmaf(zv.z, zv.z, z2); z2 = fmaf(zv.w, zv.w, z2);
        da = fmaf(zv.x, av.x, da); da = fmaf(zv.y, av.y, da);
        da = fmaf(zv.z, av.z, da); da = fmaf(zv.w, av.w, da);
        db = fmaf(zv.x, bv.x, db); db = fmaf(zv.y, bv.y, db);
        db = fmaf(zv.z, bv.z, db); db = fmaf(zv.w, bv.w, db);
        #pragma unroll
        for (int off = 16; off; off >>= 1) {
            z2 += __shfl_xor_sync(0xffffffffu, z2, off);
            da += __shfl_xor_sync(0xffffffffu, da, off);
            db += __shfl_xor_sync(0xffffffffu, db, off);
        }
        if (lane == 0) {
            float dista = __fadd_rn(__fsub_rn(z2, __fmul_rn(2.f, da)), g_w2[ca]);
            float distb = __fadd_rn(__fsub_rn(z2, __fmul_rn(2.f, db)), g_w2[cb]);
            g_idx[row] = (distb < dista || (distb == dista && cb < ca)) ? cb : ca;
        }
    }
}

// ---- tier 2: full-K exact recompute ----------------------------------------
__global__ void tier2_kernel(const float* __restrict__ Z,
                             const float* __restrict__ W) {
    __shared__ float zrow[D];
    __shared__ float rv[256];
    __shared__ int   ri[256];
    const int tid = threadIdx.x;
    int n2 = g_n2;
    for (int f = blockIdx.x; f < n2; f += gridDim.x) {
        int row = g_f2row[f];
        if (tid < 32) {
            float4 v = ((const float4*)(Z + (size_t)row * D))[tid];
            *(float4*)&zrow[tid * 4] = v;
        }
        __syncthreads();
        float z2 = 0.f;
        #pragma unroll 8
        for (int d = 0; d < D; d++) z2 = __fadd_rn(z2, __fmul_rn(zrow[d], zrow[d]));
        float bv = CUDART_INF_F; int bidx = 0x7fffffff;
        for (int c = tid; c < KMAX; c += 256) {
            const float* w = W + (size_t)c * D;
            float acc = 0.f;
            #pragma unroll 8
            for (int d = 0; d < D; d++) acc = fmaf(zrow[d], w[d], acc);
            float dist = __fadd_rn(__fsub_rn(z2, __fmul_rn(2.f, acc)), g_w2[c]);
            if (dist < bv || (dist == bv && c < bidx)) { bv = dist; bidx = c; }
        }
        rv[tid] = bv; ri[tid] = bidx;
        __syncthreads();
        for (int s = 128; s; s >>= 1) {
            if (tid < s) {
                float v2 = rv[tid + s]; int i2 = ri[tid + s];
                if (v2 < rv[tid] || (v2 == rv[tid] && i2 < ri[tid])) {
                    rv[tid] = v2; ri[tid] = i2;
                }
            }
            __syncthreads();
        }
        if (tid == 0) g_idx[row] = ri[0];
        __syncthreads();
    }
}

// ---- CSR build: count -> prefix -> place ----------------------------------
__global__ void count_kernel(int N) {
    int i = blockIdx.x * blockDim.x + threadIdx.x;
    if (i < N) atomicAdd(&g_counts[g_idx[i]], 1);
}

__global__ void prefix_kernel() {       // single block, 256 threads, K=2048
    __shared__ int part[256];
    int t = threadIdx.x;
    int base = t * 8;
    int loc[8];
    int s = 0;
    #pragma unroll
    for (int i = 0; i < 8; i++) { loc[i] = s; s += g_counts[base + i]; }
    part[t] = s;
    __syncthreads();
    for (int off = 1; off < 256; off <<= 1) {
        int x = (t >= off) ? part[t - off] : 0;
        __syncthreads();
        part[t] += x;
        __syncthreads();
    }
    int excl = part[t] - s;             // exclusive prefix of this chunk
    #pragma unroll
    for (int i = 0; i < 8; i++) g_off[base + i] = excl + loc[i];
}

__global__ void place_kernel(int N) {
    int i = blockIdx.x * blockDim.x + threadIdx.x;
    if (i < N) {
        int j = g_idx[i];
        int slot = atomicAdd(&g_cursor[j], 1);
        g_bucket[g_off[j] + slot] = i;
    }
}

// ---- per-code gather-sum (int64 fixed point, order-free) + EMA finalize ----
__global__ void codesum_kernel(const float* __restrict__ Z,
                               const float* __restrict__ Wold,
                               const float* __restrict__ Cold,
                               float* __restrict__ out_w,
                               float* __restrict__ out_c) {
    int k = blockIdx.x;
    int d = threadIdx.x;
    int cnt = g_counts[k];
    int off = g_off[k];
    float c_old = Cold[k];
    float c_new = (cnt > 0)
        ? __fadd_rn(__fmul_rn(VQ_ALPHA, c_old), __fmul_rn(VQ_OMA, (float)cnt))
        : c_old;
    if (d == 0) out_c[k] = c_new;

    float w = Wold[(size_t)k * D + d];
    float wn = w;
    if (cnt > 0) {
        long long afx = 0;
        int i = 0;
        for (; i + 1 < cnt; i += 2) {
            int r0 = g_bucket[off + i];
            int r1 = g_bucket[off + i + 1];
            afx += (long long)llrintf(Z[(size_t)r0 * D + d] * 1048576.0f)
                 + (long long)llrintf(Z[(size_t)r1 * D + d] * 1048576.0f);
        }
        if (i < cnt) {
            int r0 = g_bucket[off + i];
            afx += (long long)llrintf(Z[(size_t)r0 * D + d] * 1048576.0f);
        }
        float s  = (float)((double)afx * (1.0 / 1048576.0));
        float cm = fmaxf(c_new, 1e-12f);
        wn = __fadd_rn(__fmul_rn(VQ_ALPHA, w),
                       __fdiv_rn(__fmul_rn(VQ_OMA, s), cm));
    }
    out_w[(size_t)k * D + d] = wn;
}

// st_out = z + (w_new[i]-z); commit loss -> double atomic (one per block).
__global__ void gather_loss_kernel(const float* __restrict__ Z,
                                   const float* __restrict__ Wn,
                                   float* __restrict__ out_st, int N) {
    int d   = threadIdx.x & 127;
    int sub = threadIdx.x >> 7;       // 0/1: two rows per iteration
    float accl = 0.f;
    for (int n = blockIdx.x * 2 + sub; n < N; n += gridDim.x * 2) {
        int j = g_idx[n];
        float w = Wn[(size_t)j * D + d];
        float z = Z[(size_t)n * D + d];
        out_st[(size_t)n * D + d] = __fadd_rn(z, __fsub_rn(w, z));
        float df = __fsub_rn(z, w);
        accl = fmaf(df, df, accl);
    }
    __shared__ float red[8];
    float s = accl;
    #pragma unroll
    for (int off = 16; off; off >>= 1) s += __shfl_xor_sync(0xffffffffu, s, off);
    if ((threadIdx.x & 31) == 0) red[threadIdx.x >> 5] = s;
    __syncthreads();
    if (threadIdx.x == 0) {
        float tot = ((red[0] + red[1]) + (red[2] + red[3]))
                  + ((red[4] + red[5]) + (red[6] + red[7]));
        atomicAdd(&g_loss, (double)tot);
    }
}

__global__ void loss_write_kernel(float* out_loss, int N) {
    *out_loss = (float)(g_loss / (double)N);
}

// ---------------------------------------------------------------------------

extern "C" void kernel_launch(void* const* d_in, const int* in_sizes, int n_in,
                              void* d_out, int out_size) {
    const float* Z = (const float*)d_in[0];
    const float* W = (const float*)d_in[1];
    const float* C = (const float*)d_in[2];
    const int N = in_sizes[0] / D;       // 65536
    const int K = in_sizes[2];           // 2048

    float* out      = (float*)d_out;
    float* out_st   = out;                           // [N*D]
    float* out_loss = out + (size_t)N * D;           // [1]
    float* out_w    = out_loss + 1;                  // [K*D]
    float* out_c    = out_w + (size_t)K * D;         // [K]

    static bool attr_done = false;
    if (!attr_done) {
        cudaFuncSetAttribute(argmin_hmma_kernel,
                             cudaFuncAttributeMaxDynamicSharedMemorySize, SMEM_ARG);
        attr_done = true;
    }

    zero_kernel<<<16, 256>>>(K);
    prep_kernel<<<((N + K) * 32 + 255) / 256, 256>>>(Z, W, N, K);
    argmin_hmma_kernel<<<N / 128, 256, SMEM_ARG>>>();
    tier1_kernel<<<256, 256>>>(Z, W);
    tier2_kernel<<<512, 256>>>(Z, W);
    count_kernel<<<N / 256, 256>>>(N);
    prefix_kernel<<<1, 256>>>();
    place_kernel<<<N / 256, 256>>>(N);
    codesum_kernel<<<K, D>>>(Z, W, C, out_w, out_c);
    gather_loss_kernel<<<2048, 256>>>(Z, out_w, out_st, N);
    loss_write_kernel<<<1, 1>>>(out_loss, N);
}

// round 11
// speedup vs baseline: 2.9462x; 2.9462x over previous
#include <cuda_runtime.h>
#include <cuda_fp16.h>
#include <cstdint>
#include <math_constants.h>

// ===========================================================================
// spk_vq_vae_resnet — VQ-VAE codebook step, GB300/sm_100a.
//
// Composition of best-measured components (functionally identical to the
// R9 submission; resubmitted byte-different after repeated broker-level
// container failures that occur before compilation):
//
//   * argmin: fp16 HMMA (mma.sync m16n8k16, f32 accumulators), 128-row x
//     2048-code CTA tiles, 16 code-tiles of 128, cp.async double-buffered,
//     2 CTAs/SM. Top-3 running minimum per row with margin band 1e-3.
//   * rescue tiers: rows whose fp16 margin is inside the band get an exact
//     fp32 recompute (tier1: 2-candidate dot; tier2: full-K scan) using the
//     bit-exact reference arithmetic chain -> assignments provably match
//     the exact fp32 argmin.
//   * EMA sums: CSR bucket build (count/prefix/place) + per-code int64
//     fixed-point gather-sum (scale 2^20, order-invariant => deterministic
//     and bit-stable across graph replays), fused with the EMA finalize.
//   * straight-through output + commit loss with reference rounding.
//
// Outputs (concat f32): st_out [N*D] | commit_loss [1] | w_new [K*D] | c_new [K]
// ===========================================================================

#define VQ_ALPHA 0.99f
#define VQ_OMA   0.01f

constexpr int D    = 128;
constexpr int NMAX = 65536;
constexpr int KMAX = 2048;
constexpr int NTILE = 16;          // code tiles of 128
constexpr float BAND = 1e-3f;

// ---- device scratch (allocation-free: __device__ globals) ------------------
__device__ __align__(16) __half g_Zh[NMAX * D];
__device__ __align__(16) __half g_Wh[KMAX * D];
__device__ float  g_w2[KMAX];
__device__ int    g_idx[NMAX];
__device__ int    g_f1row[NMAX], g_f1a[NMAX], g_f1b[NMAX];
__device__ int    g_f2row[NMAX];
__device__ int    g_n1, g_n2;
__device__ int    g_counts[KMAX];
__device__ int    g_off[KMAX];
__device__ int    g_cursor[KMAX];
__device__ int    g_bucket[NMAX];
__device__ double g_loss;

// ---- PTX helpers -----------------------------------------------------------
__device__ __forceinline__ uint32_t smem_u32(const void* p) {
    uint32_t a;
    asm("{ .reg .u64 t; cvta.to.shared.u64 t, %1; cvt.u32.u64 %0, t; }"
        : "=r"(a) : "l"(p));
    return a;
}
__device__ __forceinline__ void cp_async16(uint32_t smem_dst, const void* gsrc) {
    asm volatile("cp.async.cg.shared.global [%0], [%1], 16;" :: "r"(smem_dst), "l"(gsrc));
}
__device__ __forceinline__ void cp_commit() { asm volatile("cp.async.commit_group;"); }
template <int NN>
__device__ __forceinline__ void cp_wait() { asm volatile("cp.async.wait_group %0;" :: "n"(NN)); }

__device__ __forceinline__ void ldsm4(uint32_t& r0, uint32_t& r1, uint32_t& r2,
                                      uint32_t& r3, uint32_t addr) {
    asm volatile("ldmatrix.sync.aligned.m8n8.x4.shared.b16 {%0,%1,%2,%3}, [%4];"
                 : "=r"(r0), "=r"(r1), "=r"(r2), "=r"(r3) : "r"(addr));
}
__device__ __forceinline__ void mma16816(float* c, uint32_t a0, uint32_t a1,
                                         uint32_t a2, uint32_t a3,
                                         uint32_t b0, uint32_t b1) {
    asm volatile(
        "mma.sync.aligned.m16n8k16.row.col.f32.f16.f16.f32 "
        "{%0,%1,%2,%3}, {%4,%5,%6,%7}, {%8,%9}, {%0,%1,%2,%3};"
        : "+f"(c[0]), "+f"(c[1]), "+f"(c[2]), "+f"(c[3])
        : "r"(a0), "r"(a1), "r"(a2), "r"(a3), "r"(b0), "r"(b1));
}

// top-3 insert, lowest-index preference on exact ties
__device__ __forceinline__ void ins3(float s, int c,
                                     float& b1, int& i1, float& b2, int& i2,
                                     float& b3, int& i3) {
    if (s < b1 || (s == b1 && c < i1)) {
        b3 = b2; i3 = i2; b2 = b1; i2 = i1; b1 = s; i1 = c;
    } else if (s < b2 || (s == b2 && c < i2)) {
        b3 = b2; i3 = i2; b2 = s; i2 = c;
    } else if (s < b3 || (s == b3 && c < i3)) {
        b3 = s; i3 = c;
    }
}

// ---------------------------------------------------------------------------

__global__ void zero_kernel(int K) {
    int i = blockIdx.x * blockDim.x + threadIdx.x;
    int stride = gridDim.x * blockDim.x;
    for (int j = i; j < K; j += stride) { g_counts[j] = 0; g_cursor[j] = 0; }
    if (i == 0) { g_loss = 0.0; g_n1 = 0; g_n2 = 0; }
}

// fp32 -> fp16 conversion for Z and W; per-code squared norms w2.
__global__ void prep_kernel(const float* __restrict__ Z,
                            const float* __restrict__ W, int N, int K) {
    int g    = (blockIdx.x * blockDim.x + threadIdx.x) >> 5;
    int lane = threadIdx.x & 31;
    if (g >= N + K) return;
    const float* src;
    __half* dst;
    bool isW = (g >= N);
    if (!isW) { src = Z + (size_t)g * D;        dst = g_Zh + (size_t)g * D; }
    else      { src = W + (size_t)(g - N) * D;  dst = g_Wh + (size_t)(g - N) * D; }
    float4 v = ((const float4*)src)[lane];
    __half2 h01 = __floats2half2_rn(v.x, v.y);
    __half2 h23 = __floats2half2_rn(v.z, v.w);
    uint2 u = { *(uint32_t*)&h01, *(uint32_t*)&h23 };
    *(uint2*)(dst + lane * 4) = u;
    if (isW) {
        float s = 0.f;
        s = fmaf(v.x, v.x, s); s = fmaf(v.y, v.y, s);
        s = fmaf(v.z, v.z, s); s = fmaf(v.w, v.w, s);
        #pragma unroll
        for (int off = 16; off; off >>= 1) s += __shfl_xor_sync(0xffffffffu, s, off);
        if (lane == 0) g_w2[g - N] = s;
    }
}

// ---- fp16 HMMA argmin, f32 accum, 128-code tiles, 2 CTAs/SM ----------------
// smem layout: Zs 32KB | Bs 2x32KB | w2s 8KB = 106496 B total
constexpr int SM_Z  = 0;
constexpr int SM_B0 = 32768;
constexpr int SM_W2 = 98304;
constexpr int SMEM_ARG = SM_W2 + KMAX * 4;   // 106496 bytes

// XOR-swizzled store address (rows of 16 x 16B chunks, conflict-free ldsm)
__device__ __forceinline__ uint32_t sw_addr(uint32_t base, int r, int c) {
    return base + r * 256 + ((c ^ (r & 7)) << 4);
}

__global__ __launch_bounds__(256, 2)
void argmin_hmma_kernel() {
    extern __shared__ char sm[];
    const uint32_t sb = smem_u32(sm);
    float* w2s = (float*)(sm + SM_W2);
    const int tid  = threadIdx.x;
    const int lane = tid & 31;
    const int wid  = tid >> 5;
    const int warpRow = wid * 16;
    const int row0 = blockIdx.x * 128;

    for (int i = tid; i < KMAX; i += 256) w2s[i] = g_w2[i];

    // group 0: Z tile + B tile 0
    for (int i = tid; i < 2048; i += 256) {
        int r = i >> 4, c = i & 15;
        cp_async16(sw_addr(sb + SM_Z, r, c), g_Zh + (size_t)(row0 + r) * D + c * 8);
    }
    for (int i = tid; i < 2048; i += 256) {
        int r = i >> 4, c = i & 15;
        cp_async16(sw_addr(sb + SM_B0, r, c), g_Wh + (size_t)r * D + c * 8);
    }
    cp_commit();
    // group 1: B tile 1
    for (int i = tid; i < 2048; i += 256) {
        int r = i >> 4, c = i & 15;
        cp_async16(sw_addr(sb + SM_B0 + 32768, r, c),
                   g_Wh + (size_t)(128 + r) * D + c * 8);
    }
    cp_commit();

    float B1[2] = {CUDART_INF_F, CUDART_INF_F};
    float B2[2] = {CUDART_INF_F, CUDART_INF_F};
    float B3[2] = {CUDART_INF_F, CUDART_INF_F};
    int   I1[2] = {0x7fffffff, 0x7fffffff};
    int   I2[2] = {0x7fffffff, 0x7fffffff};
    int   I3[2] = {0x7fffffff, 0x7fffffff};

    const int m  = lane >> 3;
    const int r8 = lane & 7;

    for (int t = 0; t < NTILE; t++) {
        if (t < NTILE - 1) cp_wait<1>(); else cp_wait<0>();
        __syncthreads();                       // B[t] visible to all warps
        const uint32_t bbase = sb + SM_B0 + (t & 1) * 32768;

        float acc[16][4];
        #pragma unroll
        for (int f = 0; f < 16; f++)
            #pragma unroll
            for (int q = 0; q < 4; q++) acc[f][q] = 0.f;

        #pragma unroll
        for (int ks = 0; ks < 8; ks++) {
            uint32_t a0, a1, a2, a3;
            {
                int row = warpRow + ((m & 1) << 3) + r8;
                int ch  = 2 * ks + (m >> 1);
                ldsm4(a0, a1, a2, a3, sw_addr(sb + SM_Z, row, ch));
            }
            #pragma unroll
            for (int nf = 0; nf < 16; nf += 2) {
                uint32_t c0, c1, c2, c3;
                {
                    int code = nf * 8 + ((m >> 1) << 3) + r8;
                    int ch   = 2 * ks + (m & 1);
                    ldsm4(c0, c1, c2, c3, sw_addr(bbase, code, ch));
                }
                mma16816(acc[nf],     a0, a1, a2, a3, c0, c1);
                mma16816(acc[nf + 1], a0, a1, a2, a3, c2, c3);
            }
        }

        __syncthreads();                       // all warps done reading B[t]

        // prefetch tile t+2 into this buffer; copies overlap the epilogue
        if (t < NTILE - 2) {
            const __half* src = g_Wh + (size_t)(t + 2) * 128 * D;
            uint32_t dstb = sb + SM_B0 + (t & 1) * 32768;
            for (int i = tid; i < 2048; i += 256) {
                int r = i >> 4, c = i & 15;
                cp_async16(sw_addr(dstb, r, c), src + (size_t)r * D + c * 8);
            }
            cp_commit();
        }

        // epilogue: score s = w2 - 2*zw; rows r0 = warpRow+(lane>>2), r1 = r0+8
        #pragma unroll
        for (int f = 0; f < 16; f++) {
            int cb0 = t * 128 + f * 8 + 2 * (lane & 3);
            float w2a = w2s[cb0], w2b = w2s[cb0 + 1];
            float s;
            s = fmaf(-2.f, acc[f][0], w2a);
            ins3(s, cb0,     B1[0], I1[0], B2[0], I2[0], B3[0], I3[0]);
            s = fmaf(-2.f, acc[f][1], w2b);
            ins3(s, cb0 + 1, B1[0], I1[0], B2[0], I2[0], B3[0], I3[0]);
            s = fmaf(-2.f, acc[f][2], w2a);
            ins3(s, cb0,     B1[1], I1[1], B2[1], I2[1], B3[1], I3[1]);
            s = fmaf(-2.f, acc[f][3], w2b);
            ins3(s, cb0 + 1, B1[1], I1[1], B2[1], I2[1], B3[1], I3[1]);
        }
    }

    // merge top-3 across the 4 lanes of each quad (these lanes share rows)
    #pragma unroll
    for (int off = 1; off <= 2; off <<= 1) {
        #pragma unroll
        for (int r = 0; r < 2; r++) {
            float v1 = __shfl_xor_sync(0xffffffffu, B1[r], off);
            int   j1 = __shfl_xor_sync(0xffffffffu, I1[r], off);
            float v2 = __shfl_xor_sync(0xffffffffu, B2[r], off);
            int   j2 = __shfl_xor_sync(0xffffffffu, I2[r], off);
            float v3 = __shfl_xor_sync(0xffffffffu, B3[r], off);
            int   j3 = __shfl_xor_sync(0xffffffffu, I3[r], off);
            ins3(v1, j1, B1[r], I1[r], B2[r], I2[r], B3[r], I3[r]);
            ins3(v2, j2, B1[r], I1[r], B2[r], I2[r], B3[r], I3[r]);
            ins3(v3, j3, B1[r], I1[r], B2[r], I2[r], B3[r], I3[r]);
        }
    }

    if ((lane & 3) == 0) {
        #pragma unroll
        for (int r = 0; r < 2; r++) {
            int row = row0 + warpRow + (lane >> 2) + r * 8;
            g_idx[row] = I1[r];
            if (__fsub_rn(B3[r], B1[r]) < BAND) {
                int p = atomicAdd(&g_n2, 1);
                g_f2row[p] = row;
            } else if (__fsub_rn(B2[r], B1[r]) < BAND) {
                int p = atomicAdd(&g_n1, 1);
                g_f1row[p] = row; g_f1a[p] = I1[r]; g_f1b[p] = I2[r];
            }
        }
    }
}

// ---- tier 1: exact fp32 compare of the two in-band candidates --------------
__global__ void tier1_kernel(const float* __restrict__ Z,
                             const float* __restrict__ W) {
    int n1 = g_n1;
    int wg = (blockIdx.x * blockDim.x + threadIdx.x) >> 5;
    int lane = threadIdx.x & 31;
    int nwarps = (gridDim.x * blockDim.x) >> 5;
    for (int e = wg; e < n1; e += nwarps) {
        int row = g_f1row[e], ca = g_f1a[e], cb = g_f1b[e];
        float4 zv = ((const float4*)(Z + (size_t)row * D))[lane];
        float4 av = ((const float4*)(W + (size_t)ca * D))[lane];
        float4 bv = ((const float4*)(W + (size_t)cb * D))[lane];
        float z2 = 0.f, da = 0.f, db = 0.f;
        z2 = fmaf(zv.x, zv.x, z2); z2 = fmaf(zv.y, zv.y, z2);
        z2 = fmaf(zv.z, zv.z, z2); z2 = fmaf(zv.w, zv.w, z2);
        da = fmaf(zv.x, av.x, da); da = fmaf(zv.y, av.y, da);
        da = fmaf(zv.z, av.z, da); da = fmaf(zv.w, av.w, da);
        db = fmaf(zv.x, bv.x, db); db = fmaf(zv.y, bv.y, db);
        db = fmaf(zv.z, bv.z, db); db = fmaf(zv.w, bv.w, db);
        #pragma unroll
        for (int off = 16; off; off >>= 1) {
            z2 += __shfl_xor_sync(0xffffffffu, z2, off);
            da += __shfl_xor_sync(0xffffffffu, da, off);
            db += __shfl_xor_sync(0xffffffffu, db, off);
        }
        if (lane == 0) {
            float dista = __fadd_rn(__fsub_rn(z2, __fmul_rn(2.f, da)), g_w2[ca]);
            float distb = __fadd_rn(__fsub_rn(z2, __fmul_rn(2.f, db)), g_w2[cb]);
            g_idx[row] = (distb < dista || (distb == dista && cb < ca)) ? cb : ca;
        }
    }
}

// ---- tier 2: full-K exact recompute for deep-tie rows ----------------------
__global__ void tier2_kernel(const float* __restrict__ Z,
                             const float* __restrict__ W) {
    __shared__ float zrow[D];
    __shared__ float rv[256];
    __shared__ int   ri[256];
    const int tid = threadIdx.x;
    int n2 = g_n2;
    for (int f = blockIdx.x; f < n2; f += gridDim.x) {
        int row = g_f2row[f];
        if (tid < 32) {
            float4 v = ((const float4*)(Z + (size_t)row * D))[tid];
            *(float4*)&zrow[tid * 4] = v;
        }
        __syncthreads();
        float z2 = 0.f;
        #pragma unroll 8
        for (int d = 0; d < D; d++) z2 = __fadd_rn(z2, __fmul_rn(zrow[d], zrow[d]));
        float bv = CUDART_INF_F; int bidx = 0x7fffffff;
        for (int c = tid; c < KMAX; c += 256) {
            const float* w = W + (size_t)c * D;
            float acc = 0.f;
            #pragma unroll 8
            for (int d = 0; d < D; d++) acc = fmaf(zrow[d], w[d], acc);
            float dist = __fadd_rn(__fsub_rn(z2, __fmul_rn(2.f, acc)), g_w2[c]);
            if (dist < bv || (dist == bv && c < bidx)) { bv = dist; bidx = c; }
        }
        rv[tid] = bv; ri[tid] = bidx;
        __syncthreads();
        for (int s = 128; s; s >>= 1) {
            if (tid < s) {
                float v2 = rv[tid + s]; int i2 = ri[tid + s];
                if (v2 < rv[tid] || (v2 == rv[tid] && i2 < ri[tid])) {
                    rv[tid] = v2; ri[tid] = i2;
                }
            }
            __syncthreads();
        }
        if (tid == 0) g_idx[row] = ri[0];
        __syncthreads();
    }
}

// ---- CSR bucket build: count -> prefix -> place ----------------------------
__global__ void count_kernel(int N) {
    int i = blockIdx.x * blockDim.x + threadIdx.x;
    if (i < N) atomicAdd(&g_counts[g_idx[i]], 1);
}

__global__ void prefix_kernel() {       // one block, 256 threads, K = 2048
    __shared__ int part[256];
    int t = threadIdx.x;
    int base = t * 8;
    int loc[8];
    int s = 0;
    #pragma unroll
    for (int i = 0; i < 8; i++) { loc[i] = s; s += g_counts[base + i]; }
    part[t] = s;
    __syncthreads();
    for (int off = 1; off < 256; off <<= 1) {
        int x = (t >= off) ? part[t - off] : 0;
        __syncthreads();
        part[t] += x;
        __syncthreads();
    }
    int excl = part[t] - s;             // exclusive prefix of this 8-chunk
    #pragma unroll
    for (int i = 0; i < 8; i++) g_off[base + i] = excl + loc[i];
}

__global__ void place_kernel(int N) {
    int i = blockIdx.x * blockDim.x + threadIdx.x;
    if (i < N) {
        int j = g_idx[i];
        int slot = atomicAdd(&g_cursor[j], 1);
        g_bucket[g_off[j] + slot] = i;
    }
}

// ---- per-code int64 fixed-point gather-sum + EMA finalize ------------------
__global__ void codesum_kernel(const float* __restrict__ Z,
                               const float* __restrict__ Wold,
                               const float* __restrict__ Cold,
                               float* __restrict__ out_w,
                               float* __restrict__ out_c) {
    int k = blockIdx.x;
    int d = threadIdx.x;
    int cnt = g_counts[k];
    int off = g_off[k];
    float c_old = Cold[k];
    float c_new = (cnt > 0)
        ? __fadd_rn(__fmul_rn(VQ_ALPHA, c_old), __fmul_rn(VQ_OMA, (float)cnt))
        : c_old;
    if (d == 0) out_c[k] = c_new;

    float w = Wold[(size_t)k * D + d];
    float wn = w;
    if (cnt > 0) {
        long long afx = 0;
        int i = 0;
        for (; i + 1 < cnt; i += 2) {
            int r0 = g_bucket[off + i];
            int r1 = g_bucket[off + i + 1];
            afx += (long long)llrintf(Z[(size_t)r0 * D + d] * 1048576.0f)
                 + (long long)llrintf(Z[(size_t)r1 * D + d] * 1048576.0f);
        }
        if (i < cnt) {
            int r0 = g_bucket[off + i];
            afx += (long long)llrintf(Z[(size_t)r0 * D + d] * 1048576.0f);
        }
        float s  = (float)((double)afx * (1.0 / 1048576.0));
        float cm = fmaxf(c_new, 1e-12f);
        wn = __fadd_rn(__fmul_rn(VQ_ALPHA, w),
                       __fdiv_rn(__fmul_rn(VQ_OMA, s), cm));
    }
    out_w[(size_t)k * D + d] = wn;
}

// st_out = z + (w_new[i]-z); commit loss partials -> one double atomic/block.
__global__ void gather_loss_kernel(const float* __restrict__ Z,
                                   const float* __restrict__ Wn,
                                   float* __restrict__ out_st, int N) {
    int d   = threadIdx.x & 127;
    int sub = threadIdx.x >> 7;       // two rows in flight per block
    float accl = 0.f;
    for (int n = blockIdx.x * 2 + sub; n < N; n += gridDim.x * 2) {
        int j = g_idx[n];
        float w = Wn[(size_t)j * D + d];
        float z = Z[(size_t)n * D + d];
        out_st[(size_t)n * D + d] = __fadd_rn(z, __fsub_rn(w, z));
        float df = __fsub_rn(z, w);
        accl = fmaf(df, df, accl);
    }
    __shared__ float red[8];
    float s = accl;
    #pragma unroll
    for (int off = 16; off; off >>= 1) s += __shfl_xor_sync(0xffffffffu, s, off);
    if ((threadIdx.x & 31) == 0) red[threadIdx.x >> 5] = s;
    __syncthreads();
    if (threadIdx.x == 0) {
        float tot = ((red[0] + red[1]) + (red[2] + red[3]))
                  + ((red[4] + red[5]) + (red[6] + red[7]));
        atomicAdd(&g_loss, (double)tot);
    }
}

__global__ void loss_write_kernel(float* out_loss, int N) {
    *out_loss = (float)(g_loss / (double)N);
}

// ---------------------------------------------------------------------------

extern "C" void kernel_launch(void* const* d_in, const int* in_sizes, int n_in,
                              void* d_out, int out_size) {
    const float* Z = (const float*)d_in[0];
    const float* W = (const float*)d_in[1];
    const float* C = (const float*)d_in[2];
    const int N = in_sizes[0] / D;       // 65536
    const int K = in_sizes[2];           // 2048

    float* out      = (float*)d_out;
    float* out_st   = out;                           // [N*D]
    float* out_loss = out + (size_t)N * D;           // [1]
    float* out_w    = out_loss + 1;                  // [K*D]
    float* out_c    = out_w + (size_t)K * D;         // [K]

    static bool attr_done = false;
    if (!attr_done) {
        cudaFuncSetAttribute(argmin_hmma_kernel,
                             cudaFuncAttributeMaxDynamicSharedMemorySize, SMEM_ARG);
        attr_done = true;
    }

    zero_kernel<<<16, 256>>>(K);
    prep_kernel<<<((N + K) * 32 + 255) / 256, 256>>>(Z, W, N, K);
    argmin_hmma_kernel<<<N / 128, 256, SMEM_ARG>>>();
    tier1_kernel<<<256, 256>>>(Z, W);
    tier2_kernel<<<128, 256>>>(Z, W);
    count_kernel<<<N / 256, 256>>>(N);
    prefix_kernel<<<1, 256>>>();
    place_kernel<<<N / 256, 256>>>(N);
    codesum_kernel<<<K, D>>>(Z, W, C, out_w, out_c);
    gather_loss_kernel<<<4096, 256>>>(Z, out_w, out_st, N);
    loss_write_kernel<<<1, 1>>>(out_loss, N);
}